// round 3
// baseline (speedup 1.0000x reference)
#include <cuda_runtime.h>
#include <cstdint>

#define N_NODES 100000
#define N_EDGES 1600000
#define F_IN    256
#define H_DIM   32
#define P_DIM   512
#define A_DIM   64

// ---------------- scratch (static __device__, allocation-free) ----------------
__device__ float g_deg [N_NODES];
__device__ float g_dinv[N_NODES];
__device__ float g_xw  [N_NODES * H_DIM];   // x @ W (pre-aggregation)
__device__ float g_agg [N_NODES * H_DIM];   // edge-aggregated
__device__ float g_h   [N_NODES * H_DIM];   // post-relu hidden

// ---------------- packed f32x2 helpers (FFMA2 path, sm_100+) ----------------
__device__ __forceinline__ unsigned long long pack2(float x, float y) {
    unsigned long long r;
    asm("mov.b64 %0, {%1, %2};" : "=l"(r) : "f"(x), "f"(y));
    return r;
}
__device__ __forceinline__ void fma2(unsigned long long& d, unsigned long long a, unsigned long long b) {
    asm("fma.rn.f32x2 %0, %1, %2, %0;" : "+l"(d) : "l"(a), "l"(b));
}
__device__ __forceinline__ float2 unpack2(unsigned long long v) {
    float2 f;
    asm("mov.b64 {%0, %1}, %2;" : "=f"(f.x), "=f"(f.y) : "l"(v));
    return f;
}

// ---------------- tiny kernels ----------------
__global__ void k_zero4(float* __restrict__ p, int n4) {
    int i = blockIdx.x * blockDim.x + threadIdx.x;
    if (i < n4) ((float4*)p)[i] = make_float4(0.f, 0.f, 0.f, 0.f);
}

__global__ void k_degree(const int* __restrict__ ei, float* __restrict__ deg) {
    int e = blockIdx.x * blockDim.x + threadIdx.x;
    if (e < N_EDGES) atomicAdd(&deg[__ldg(&ei[N_EDGES + e])], 1.0f);
}

__global__ void k_dinv(const float* __restrict__ deg, float* __restrict__ dinv) {
    int i = blockIdx.x * blockDim.x + threadIdx.x;
    if (i < N_NODES) dinv[i] = rsqrtf(deg[i] + 1.0f);   // +1 = self loop; always > 0
}

// agg[n][k] + self-loop + bias + relu
__global__ void k_finish(const float* __restrict__ agg, const float* __restrict__ xw,
                         const float* __restrict__ dinv, const float* __restrict__ b,
                         float* __restrict__ out) {
    int idx = blockIdx.x * blockDim.x + threadIdx.x;
    if (idx < N_NODES * H_DIM) {
        int n = idx >> 5, k = idx & 31;
        float d = dinv[n];
        float v = agg[idx] + xw[idx] * d * d + b[k];
        out[idx] = fmaxf(v, 0.f);
    }
}

// ---------------- edge aggregation: 8 lanes per edge, vector atomics ----------------
__global__ void k_edge(const int* __restrict__ ei, const float* __restrict__ xw,
                       const float* __restrict__ dinv, float* __restrict__ agg) {
    int lane = threadIdx.x & 31;
    int warp = (blockIdx.x * blockDim.x + threadIdx.x) >> 5;
    int nwarps = (gridDim.x * blockDim.x) >> 5;
    int sub = lane >> 3;        // edge within group of 4
    int q   = lane & 7;         // float4 slot (8 * 4 = 32 floats)

    for (int base = warp * 4; base < N_EDGES; base += nwarps * 4) {
        int e = base + sub;
        if (e < N_EDGES) {
            int src = __ldg(&ei[e]);
            int dst = __ldg(&ei[N_EDGES + e]);
            float norm = dinv[src] * dinv[dst];
            float4 v = ((const float4*)xw)[src * 8 + q];
            v.x *= norm; v.y *= norm; v.z *= norm; v.w *= norm;
            float* p = agg + ((long long)dst * H_DIM + q * 4);
            asm volatile("red.global.add.v4.f32 [%0], {%1, %2, %3, %4};"
                         :: "l"(p), "f"(v.x), "f"(v.y), "f"(v.z), "f"(v.w) : "memory");
        }
    }
}

// ---------------- GEMM: features[N,256] @ W1[256,32] -> g_xw ----------------
__global__ __launch_bounds__(128) void k_gemm_fw1(const float* __restrict__ feat,
                                                  const float* __restrict__ W1,
                                                  float* __restrict__ out) {
    __shared__ float sW[64 * 32];        // one k-chunk of W1
    __shared__ float sF[128 * 65];       // 128 nodes x 64 k (padded stride 65)
    int tid  = threadIdx.x;
    int base = blockIdx.x * 128;
    int n    = base + tid;

    float acc[32];
#pragma unroll
    for (int h = 0; h < 32; h++) acc[h] = 0.f;

    for (int kc = 0; kc < 4; kc++) {
        __syncthreads();
        for (int i = tid; i < 64 * 32; i += 128) sW[i] = W1[kc * 2048 + i];
        for (int i = tid; i < 128 * 64; i += 128) {
            int r = i >> 6, c = i & 63;
            int nn = base + r;
            sF[r * 65 + c] = (nn < N_NODES) ? feat[(long long)nn * F_IN + kc * 64 + c] : 0.f;
        }
        __syncthreads();
#pragma unroll 4
        for (int k = 0; k < 64; k++) {
            float f = sF[tid * 65 + k];
            const float4* w4 = (const float4*)&sW[k * 32];
#pragma unroll
            for (int h4 = 0; h4 < 8; h4++) {
                float4 w = w4[h4];
                acc[h4 * 4 + 0] += f * w.x;
                acc[h4 * 4 + 1] += f * w.y;
                acc[h4 * 4 + 2] += f * w.z;
                acc[h4 * 4 + 3] += f * w.w;
            }
        }
    }
    if (n < N_NODES) {
        float4* o = (float4*)(out + (long long)n * H_DIM);
#pragma unroll
        for (int h4 = 0; h4 < 8; h4++)
            o[h4] = make_float4(acc[h4 * 4], acc[h4 * 4 + 1], acc[h4 * 4 + 2], acc[h4 * 4 + 3]);
    }
}

// ---------------- GEMM: h[N,32] @ W2[32,32] -> g_xw ----------------
__global__ __launch_bounds__(128) void k_gemm_hw2(const float* __restrict__ hin,
                                                  const float* __restrict__ W2,
                                                  float* __restrict__ out) {
    __shared__ float sW[32 * 32];
    __shared__ float sH[128 * 33];
    int tid  = threadIdx.x;
    int base = blockIdx.x * 128;
    int n    = base + tid;

    for (int i = tid; i < 1024; i += 128) sW[i] = W2[i];
    for (int i = tid; i < 128 * 32; i += 128) {
        int r = i >> 5, c = i & 31;
        int nn = base + r;
        sH[r * 33 + c] = (nn < N_NODES) ? hin[(long long)nn * H_DIM + c] : 0.f;
    }
    __syncthreads();

    float acc[32];
#pragma unroll
    for (int h = 0; h < 32; h++) acc[h] = 0.f;
#pragma unroll 4
    for (int k = 0; k < 32; k++) {
        float f = sH[tid * 33 + k];
        const float4* w4 = (const float4*)&sW[k * 32];
#pragma unroll
        for (int h4 = 0; h4 < 8; h4++) {
            float4 w = w4[h4];
            acc[h4 * 4 + 0] += f * w.x;
            acc[h4 * 4 + 1] += f * w.y;
            acc[h4 * 4 + 2] += f * w.z;
            acc[h4 * 4 + 3] += f * w.w;
        }
    }
    if (n < N_NODES) {
        float4* o = (float4*)(out + (long long)n * H_DIM);
#pragma unroll
        for (int h4 = 0; h4 < 8; h4++)
            o[h4] = make_float4(acc[h4 * 4], acc[h4 * 4 + 1], acc[h4 * 4 + 2], acc[h4 * 4 + 3]);
    }
}

// ---------------- fused MLP heads: 32 nodes/block, 256 threads ----------------
// thread t: node nl = t>>3, output-octet oct = t&7 (8 of 64 policy cols / 8 of 64 u-cols)
__global__ __launch_bounds__(256) void k_head(const float* __restrict__ h,
    const float* __restrict__ pW1, const float* __restrict__ pb1,
    const float* __restrict__ pW2, const float* __restrict__ pb2,
    const float* __restrict__ vW1, const float* __restrict__ vb1,
    const float* __restrict__ vW2, const float* __restrict__ vb2,
    float* __restrict__ out)
{
    __shared__ float sh [32 * 33];   // h tile
    __shared__ float sW1[32 * 64];   // layer-1 weight chunk
    __shared__ float sW2[64 * 64];   // layer-2 weight chunk (policy)
    __shared__ float su [32 * 68];   // relu(u) chunk
    __shared__ float sv2[64];        // vW2 chunk

    int tid = threadIdx.x;
    int nl  = tid >> 3;
    int oct = tid & 7;
    int nodeBase = blockIdx.x * 32;      // 3125 * 32 == 100000, exact
    int n = nodeBase + nl;

    for (int i = tid; i < 32 * 32; i += 256) {
        int r = i >> 5, c = i & 31;
        sh[r * 33 + c] = h[(long long)(nodeBase + r) * H_DIM + c];
    }
    __syncthreads();

    float hreg[32];
#pragma unroll
    for (int k = 0; k < 32; k++) hreg[k] = sh[nl * 33 + k];

    unsigned long long pacc[4];
#pragma unroll
    for (int p = 0; p < 4; p++) pacc[p] = 0ull;

    // ---------- policy path ----------
    for (int jc = 0; jc < 8; jc++) {
        __syncthreads();
        for (int i = tid; i < 2048; i += 256) {
            int k = i >> 6, c = i & 63;
            sW1[i] = pW1[k * P_DIM + jc * 64 + c];
        }
        for (int i = tid; i < 4096; i += 256) sW2[i] = pW2[jc * 4096 + i];
        __syncthreads();

        int jb = jc * 64 + oct * 8;
        unsigned long long u0 = pack2(pb1[jb + 0], pb1[jb + 1]);
        unsigned long long u1 = pack2(pb1[jb + 2], pb1[jb + 3]);
        unsigned long long u2 = pack2(pb1[jb + 4], pb1[jb + 5]);
        unsigned long long u3 = pack2(pb1[jb + 6], pb1[jb + 7]);
#pragma unroll
        for (int k = 0; k < 32; k++) {
            unsigned long long hk = pack2(hreg[k], hreg[k]);
            const ulonglong2* w = (const ulonglong2*)&sW1[k * 64 + oct * 8];
            ulonglong2 wa = w[0], wb = w[1];
            fma2(u0, hk, wa.x); fma2(u1, hk, wa.y);
            fma2(u2, hk, wb.x); fma2(u3, hk, wb.y);
        }
        float2 a0 = unpack2(u0), a1 = unpack2(u1), a2 = unpack2(u2), a3 = unpack2(u3);
        float* sp = &su[nl * 68 + oct * 8];
        *(float4*)(sp + 0) = make_float4(fmaxf(a0.x, 0.f), fmaxf(a0.y, 0.f),
                                         fmaxf(a1.x, 0.f), fmaxf(a1.y, 0.f));
        *(float4*)(sp + 4) = make_float4(fmaxf(a2.x, 0.f), fmaxf(a2.y, 0.f),
                                         fmaxf(a3.x, 0.f), fmaxf(a3.y, 0.f));
        __syncthreads();

#pragma unroll 4
        for (int j = 0; j < 64; j++) {
            float uv = su[nl * 68 + j];
            unsigned long long up = pack2(uv, uv);
            const ulonglong2* w = (const ulonglong2*)&sW2[j * 64 + oct * 8];
            ulonglong2 wa = w[0], wb = w[1];
            fma2(pacc[0], up, wa.x); fma2(pacc[1], up, wa.y);
            fma2(pacc[2], up, wb.x); fma2(pacc[3], up, wb.y);
        }
    }
    // write policy
    {
        int ab = oct * 8;
        float2 p0 = unpack2(pacc[0]), p1 = unpack2(pacc[1]);
        float2 p2 = unpack2(pacc[2]), p3 = unpack2(pacc[3]);
        float4* o = (float4*)(out + (long long)n * A_DIM + ab);
        o[0] = make_float4(p0.x + pb2[ab + 0], p0.y + pb2[ab + 1],
                           p1.x + pb2[ab + 2], p1.y + pb2[ab + 3]);
        o[1] = make_float4(p2.x + pb2[ab + 4], p2.y + pb2[ab + 5],
                           p3.x + pb2[ab + 6], p3.y + pb2[ab + 7]);
    }

    // ---------- value path ----------
    float vpart = 0.f;
    for (int jc = 0; jc < 8; jc++) {
        __syncthreads();
        for (int i = tid; i < 2048; i += 256) {
            int k = i >> 6, c = i & 63;
            sW1[i] = vW1[k * P_DIM + jc * 64 + c];
        }
        if (tid < 64) sv2[tid] = vW2[jc * 64 + tid];
        __syncthreads();

        int jb = jc * 64 + oct * 8;
        unsigned long long u0 = pack2(vb1[jb + 0], vb1[jb + 1]);
        unsigned long long u1 = pack2(vb1[jb + 2], vb1[jb + 3]);
        unsigned long long u2 = pack2(vb1[jb + 4], vb1[jb + 5]);
        unsigned long long u3 = pack2(vb1[jb + 6], vb1[jb + 7]);
#pragma unroll
        for (int k = 0; k < 32; k++) {
            unsigned long long hk = pack2(hreg[k], hreg[k]);
            const ulonglong2* w = (const ulonglong2*)&sW1[k * 64 + oct * 8];
            ulonglong2 wa = w[0], wb = w[1];
            fma2(u0, hk, wa.x); fma2(u1, hk, wa.y);
            fma2(u2, hk, wb.x); fma2(u3, hk, wb.y);
        }
        float2 a0 = unpack2(u0), a1 = unpack2(u1), a2 = unpack2(u2), a3 = unpack2(u3);
        const float* s2 = &sv2[oct * 8];
        vpart += fmaxf(a0.x, 0.f) * s2[0] + fmaxf(a0.y, 0.f) * s2[1]
               + fmaxf(a1.x, 0.f) * s2[2] + fmaxf(a1.y, 0.f) * s2[3]
               + fmaxf(a2.x, 0.f) * s2[4] + fmaxf(a2.y, 0.f) * s2[5]
               + fmaxf(a3.x, 0.f) * s2[6] + fmaxf(a3.y, 0.f) * s2[7];
    }
    vpart += __shfl_down_sync(0xffffffffu, vpart, 4);
    vpart += __shfl_down_sync(0xffffffffu, vpart, 2);
    vpart += __shfl_down_sync(0xffffffffu, vpart, 1);
    if (oct == 0) out[(long long)N_NODES * A_DIM + n] = vpart + vb2[0];
}

// ---------------- launch ----------------
extern "C" void kernel_launch(void* const* d_in, const int* in_sizes, int n_in,
                              void* d_out, int out_size) {
    const float* feat = (const float*)d_in[0];
    const int*   ei   = (const int*)d_in[1];      // int32: JAX x64 disabled downcasts int64
    const float* W1  = (const float*)d_in[2];
    const float* b1  = (const float*)d_in[3];
    const float* W2  = (const float*)d_in[4];
    const float* b2  = (const float*)d_in[5];
    const float* pW1 = (const float*)d_in[6];
    const float* pb1 = (const float*)d_in[7];
    const float* pW2 = (const float*)d_in[8];
    const float* pb2 = (const float*)d_in[9];
    const float* vW1 = (const float*)d_in[10];
    const float* vb1 = (const float*)d_in[11];
    const float* vW2 = (const float*)d_in[12];
    const float* vb2 = (const float*)d_in[13];
    float* out = (float*)d_out;

    float *p_deg, *p_dinv, *p_xw, *p_agg, *p_h;
    cudaGetSymbolAddress((void**)&p_deg,  g_deg);
    cudaGetSymbolAddress((void**)&p_dinv, g_dinv);
    cudaGetSymbolAddress((void**)&p_xw,   g_xw);
    cudaGetSymbolAddress((void**)&p_agg,  g_agg);
    cudaGetSymbolAddress((void**)&p_h,    g_h);

    const int T = 256;
    // degree + dinv
    k_zero4<<<(N_NODES / 4 + T - 1) / T, T>>>(p_deg, N_NODES / 4);
    k_degree<<<(N_EDGES + T - 1) / T, T>>>(ei, p_deg);
    k_dinv<<<(N_NODES + T - 1) / T, T>>>(p_deg, p_dinv);

    // conv1
    k_gemm_fw1<<<(N_NODES + 127) / 128, 128>>>(feat, W1, p_xw);
    k_zero4<<<(N_NODES * H_DIM / 4 + T - 1) / T, T>>>(p_agg, N_NODES * H_DIM / 4);
    k_edge<<<148 * 8, T>>>(ei, p_xw, p_dinv, p_agg);
    k_finish<<<(N_NODES * H_DIM + T - 1) / T, T>>>(p_agg, p_xw, p_dinv, b1, p_h);

    // conv2
    k_gemm_hw2<<<(N_NODES + 127) / 128, 128>>>(p_h, W2, p_xw);
    k_zero4<<<(N_NODES * H_DIM / 4 + T - 1) / T, T>>>(p_agg, N_NODES * H_DIM / 4);
    k_edge<<<148 * 8, T>>>(ei, p_xw, p_dinv, p_agg);
    k_finish<<<(N_NODES * H_DIM + T - 1) / T, T>>>(p_agg, p_xw, p_dinv, b2, p_h);

    // heads
    k_head<<<N_NODES / 32, 256>>>(p_h, pW1, pb1, pW2, pb2, vW1, vb1, vW2, vb2, out);
}

// round 5
// speedup vs baseline: 1.0539x; 1.0539x over previous
#include <cuda_runtime.h>
#include <cstdint>

#define N_NODES 100000
#define N_EDGES 1600000
#define F_IN    256
#define H_DIM   32
#define P_DIM   512
#define A_DIM   64

#define SCAN_T  512
#define SCAN_NB 196   // 196*512 = 100352 >= N_NODES

// ---------------- scratch (static __device__, allocation-free) ----------------
__device__ int   g_cnt   [N_NODES];
__device__ int   g_rowst [N_NODES];
__device__ int   g_cursor[N_NODES];
__device__ int   g_sums  [SCAN_T];          // block sums for scan (>= SCAN_NB)
__device__ int   g_csr   [N_EDGES];         // src ids grouped by dst
__device__ float g_dinv  [N_NODES];
__device__ float g_xw    [N_NODES * H_DIM];
__device__ float g_h     [N_NODES * H_DIM];

// ---------------- packed f32x2 helpers ----------------
__device__ __forceinline__ unsigned long long pack2(float x, float y) {
    unsigned long long r;
    asm("mov.b64 %0, {%1, %2};" : "=l"(r) : "f"(x), "f"(y));
    return r;
}
__device__ __forceinline__ void fma2(unsigned long long& d, unsigned long long a, unsigned long long b) {
    asm("fma.rn.f32x2 %0, %1, %2, %0;" : "+l"(d) : "l"(a), "l"(b));
}
__device__ __forceinline__ float2 unpack2(unsigned long long v) {
    float2 f;
    asm("mov.b64 {%0, %1}, %2;" : "=f"(f.x), "=f"(f.y) : "l"(v));
    return f;
}

// ================= CSR build =================
__global__ void k_zeroi(int* __restrict__ p, int n) {
    int i = blockIdx.x * blockDim.x + threadIdx.x;
    if (i < n) p[i] = 0;
}

__global__ void k_count(const int* __restrict__ ei, int* __restrict__ cnt) {
    int e = blockIdx.x * blockDim.x + threadIdx.x;
    if (e < N_EDGES) atomicAdd(&cnt[__ldg(&ei[N_EDGES + e])], 1);
}

__global__ void k_scan1(const int* __restrict__ cnt, int* __restrict__ incl,
                        int* __restrict__ sums) {
    __shared__ int s[SCAN_T];
    int t = threadIdx.x;
    int i = blockIdx.x * SCAN_T + t;
    int v = (i < N_NODES) ? cnt[i] : 0;
    s[t] = v;
    __syncthreads();
#pragma unroll
    for (int off = 1; off < SCAN_T; off <<= 1) {
        int a = (t >= off) ? s[t - off] : 0;
        __syncthreads();
        s[t] += a;
        __syncthreads();
    }
    if (i < N_NODES) incl[i] = s[t];
    if (t == SCAN_T - 1) sums[blockIdx.x] = s[t];
}

__global__ void k_scan2(int* __restrict__ sums) {
    __shared__ int s[256];
    int t = threadIdx.x;
    int v = (t < SCAN_NB) ? sums[t] : 0;
    s[t] = v;
    __syncthreads();
#pragma unroll
    for (int off = 1; off < 256; off <<= 1) {
        int a = (t >= off) ? s[t - off] : 0;
        __syncthreads();
        s[t] += a;
        __syncthreads();
    }
    sums[t] = s[t] - v;   // exclusive
}

__global__ void k_scan3(const int* __restrict__ cnt, int* __restrict__ rowst,
                        const int* __restrict__ sums, int* __restrict__ cursor,
                        float* __restrict__ dinv) {
    int t = threadIdx.x;
    int i = blockIdx.x * SCAN_T + t;
    if (i < N_NODES) {
        int c = cnt[i];
        int excl = rowst[i] - c + sums[blockIdx.x];
        rowst[i]  = excl;
        cursor[i] = excl;
        dinv[i]   = rsqrtf((float)c + 1.0f);   // +1 = self-loop
    }
}

__global__ void k_scatter(const int* __restrict__ ei, int* __restrict__ cursor,
                          int* __restrict__ csr) {
    int e = blockIdx.x * blockDim.x + threadIdx.x;
    if (e < N_EDGES) {
        int dst = __ldg(&ei[N_EDGES + e]);
        int pos = atomicAdd(&cursor[dst], 1);
        csr[pos] = __ldg(&ei[e]);
    }
}

// ================= CSR aggregation (atomic-free, fused finish) =================
// out[n] = relu( dinv[n] * sum_{src in in(n)} xw[src]*dinv[src]
//                + dinv[n]^2 * xw[n] + b )
__global__ __launch_bounds__(256) void k_aggr(const float* __restrict__ xw,
                                              const float* __restrict__ dinv,
                                              const int* __restrict__ cnt,
                                              const int* __restrict__ rowst,
                                              const int* __restrict__ csr,
                                              const float* __restrict__ b,
                                              float* __restrict__ out) {
    int idx = blockIdx.x * blockDim.x + threadIdx.x;
    int n = idx >> 3;
    int q = idx & 7;
    if (n >= N_NODES) return;

    int start = __ldg(&rowst[n]);
    int deg   = __ldg(&cnt[n]);
    float4 acc = make_float4(0.f, 0.f, 0.f, 0.f);

    int src_n = (deg > 0) ? __ldg(&csr[start]) : 0;
    for (int j = 0; j < deg; j++) {
        int src = src_n;
        if (j + 1 < deg) src_n = __ldg(&csr[start + j + 1]);
        float ds = __ldg(&dinv[src]);
        float4 v = __ldg(&((const float4*)xw)[src * 8 + q]);
        acc.x = fmaf(v.x, ds, acc.x);
        acc.y = fmaf(v.y, ds, acc.y);
        acc.z = fmaf(v.z, ds, acc.z);
        acc.w = fmaf(v.w, ds, acc.w);
    }
    float dd  = __ldg(&dinv[n]);
    float dd2 = dd * dd;
    float4 sv = __ldg(&((const float4*)xw)[n * 8 + q]);
    float4 bb = __ldg(&((const float4*)b)[q]);
    float4 r;
    r.x = fmaxf(fmaf(acc.x, dd, fmaf(sv.x, dd2, bb.x)), 0.f);
    r.y = fmaxf(fmaf(acc.y, dd, fmaf(sv.y, dd2, bb.y)), 0.f);
    r.z = fmaxf(fmaf(acc.z, dd, fmaf(sv.z, dd2, bb.z)), 0.f);
    r.w = fmaxf(fmaf(acc.w, dd, fmaf(sv.w, dd2, bb.w)), 0.f);
    ((float4*)out)[n * 8 + q] = r;
}

// ================= GEMM1: features[N,256] @ W1[256,32] (W-stationary) =================
__global__ __launch_bounds__(128) void k_gemm_fw1(const float* __restrict__ feat,
                                                  const float* __restrict__ W1,
                                                  float* __restrict__ out) {
    __shared__ float sW[F_IN * H_DIM];     // 32 KB, whole W1
    int tid = threadIdx.x;
    for (int i = tid; i < F_IN * H_DIM; i += 128) sW[i] = W1[i];
    __syncthreads();

    int n = blockIdx.x * 128 + tid;
    if (n >= N_NODES) return;

    const float4* fr = (const float4*)(feat + (long long)n * F_IN);
    unsigned long long acc[16];
#pragma unroll
    for (int i = 0; i < 16; i++) acc[i] = 0ull;

#pragma unroll 2
    for (int k4 = 0; k4 < F_IN / 4; k4++) {
        float4 f = __ldg(&fr[k4]);
        float fv[4] = {f.x, f.y, f.z, f.w};
#pragma unroll
        for (int s = 0; s < 4; s++) {
            int k = k4 * 4 + s;
            unsigned long long hk = pack2(fv[s], fv[s]);
            const ulonglong2* w = (const ulonglong2*)&sW[k * H_DIM];
#pragma unroll
            for (int p = 0; p < 8; p++) {
                ulonglong2 ww = w[p];
                fma2(acc[p * 2 + 0], hk, ww.x);
                fma2(acc[p * 2 + 1], hk, ww.y);
            }
        }
    }
    float4* o = (float4*)(out + (long long)n * H_DIM);
#pragma unroll
    for (int p = 0; p < 8; p++) {
        float2 a = unpack2(acc[p * 2]), c = unpack2(acc[p * 2 + 1]);
        o[p] = make_float4(a.x, a.y, c.x, c.y);
    }
}

// ================= GEMM2: h[N,32] @ W2[32,32] (W-stationary) =================
__global__ __launch_bounds__(128) void k_gemm_hw2(const float* __restrict__ hin,
                                                  const float* __restrict__ W2,
                                                  float* __restrict__ out) {
    __shared__ float sW[H_DIM * H_DIM];    // 4 KB
    int tid = threadIdx.x;
    for (int i = tid; i < H_DIM * H_DIM; i += 128) sW[i] = W2[i];
    __syncthreads();

    int n = blockIdx.x * 128 + tid;
    if (n >= N_NODES) return;

    const float4* fr = (const float4*)(hin + (long long)n * H_DIM);
    unsigned long long acc[16];
#pragma unroll
    for (int i = 0; i < 16; i++) acc[i] = 0ull;

#pragma unroll 2
    for (int k4 = 0; k4 < H_DIM / 4; k4++) {
        float4 f = __ldg(&fr[k4]);
        float fv[4] = {f.x, f.y, f.z, f.w};
#pragma unroll
        for (int s = 0; s < 4; s++) {
            int k = k4 * 4 + s;
            unsigned long long hk = pack2(fv[s], fv[s]);
            const ulonglong2* w = (const ulonglong2*)&sW[k * H_DIM];
#pragma unroll
            for (int p = 0; p < 8; p++) {
                ulonglong2 ww = w[p];
                fma2(acc[p * 2 + 0], hk, ww.x);
                fma2(acc[p * 2 + 1], hk, ww.y);
            }
        }
    }
    float4* o = (float4*)(out + (long long)n * H_DIM);
#pragma unroll
    for (int p = 0; p < 8; p++) {
        float2 a = unpack2(acc[p * 2]), c = unpack2(acc[p * 2 + 1]);
        o[p] = make_float4(a.x, a.y, c.x, c.y);
    }
}

// ================= fused MLP heads (unchanged from passing R3 kernel) =================
__global__ __launch_bounds__(256) void k_head(const float* __restrict__ h,
    const float* __restrict__ pW1, const float* __restrict__ pb1,
    const float* __restrict__ pW2, const float* __restrict__ pb2,
    const float* __restrict__ vW1, const float* __restrict__ vb1,
    const float* __restrict__ vW2, const float* __restrict__ vb2,
    float* __restrict__ out)
{
    __shared__ float sh [32 * 33];
    __shared__ float sW1[32 * 64];
    __shared__ float sW2[64 * 64];
    __shared__ float su [32 * 68];
    __shared__ float sv2[64];

    int tid = threadIdx.x;
    int nl  = tid >> 3;
    int oct = tid & 7;
    int nodeBase = blockIdx.x * 32;
    int n = nodeBase + nl;

    for (int i = tid; i < 32 * 32; i += 256) {
        int r = i >> 5, c = i & 31;
        sh[r * 33 + c] = h[(long long)(nodeBase + r) * H_DIM + c];
    }
    __syncthreads();

    float hreg[32];
#pragma unroll
    for (int k = 0; k < 32; k++) hreg[k] = sh[nl * 33 + k];

    unsigned long long pacc[4];
#pragma unroll
    for (int p = 0; p < 4; p++) pacc[p] = 0ull;

    for (int jc = 0; jc < 8; jc++) {
        __syncthreads();
        for (int i = tid; i < 2048; i += 256) {
            int k = i >> 6, c = i & 63;
            sW1[i] = pW1[k * P_DIM + jc * 64 + c];
        }
        for (int i = tid; i < 4096; i += 256) sW2[i] = pW2[jc * 4096 + i];
        __syncthreads();

        int jb = jc * 64 + oct * 8;
        unsigned long long u0 = pack2(pb1[jb + 0], pb1[jb + 1]);
        unsigned long long u1 = pack2(pb1[jb + 2], pb1[jb + 3]);
        unsigned long long u2 = pack2(pb1[jb + 4], pb1[jb + 5]);
        unsigned long long u3 = pack2(pb1[jb + 6], pb1[jb + 7]);
#pragma unroll
        for (int k = 0; k < 32; k++) {
            unsigned long long hk = pack2(hreg[k], hreg[k]);
            const ulonglong2* w = (const ulonglong2*)&sW1[k * 64 + oct * 8];
            ulonglong2 wa = w[0], wb = w[1];
            fma2(u0, hk, wa.x); fma2(u1, hk, wa.y);
            fma2(u2, hk, wb.x); fma2(u3, hk, wb.y);
        }
        float2 a0 = unpack2(u0), a1 = unpack2(u1), a2 = unpack2(u2), a3 = unpack2(u3);
        float* sp = &su[nl * 68 + oct * 8];
        *(float4*)(sp + 0) = make_float4(fmaxf(a0.x, 0.f), fmaxf(a0.y, 0.f),
                                         fmaxf(a1.x, 0.f), fmaxf(a1.y, 0.f));
        *(float4*)(sp + 4) = make_float4(fmaxf(a2.x, 0.f), fmaxf(a2.y, 0.f),
                                         fmaxf(a3.x, 0.f), fmaxf(a3.y, 0.f));
        __syncthreads();

#pragma unroll 4
        for (int j = 0; j < 64; j++) {
            float uv = su[nl * 68 + j];
            unsigned long long up = pack2(uv, uv);
            const ulonglong2* w = (const ulonglong2*)&sW2[j * 64 + oct * 8];
            ulonglong2 wa = w[0], wb = w[1];
            fma2(pacc[0], up, wa.x); fma2(pacc[1], up, wa.y);
            fma2(pacc[2], up, wb.x); fma2(pacc[3], up, wb.y);
        }
    }
    {
        int ab = oct * 8;
        float2 p0 = unpack2(pacc[0]), p1 = unpack2(pacc[1]);
        float2 p2 = unpack2(pacc[2]), p3 = unpack2(pacc[3]);
        float4* o = (float4*)(out + (long long)n * A_DIM + ab);
        o[0] = make_float4(p0.x + pb2[ab + 0], p0.y + pb2[ab + 1],
                           p1.x + pb2[ab + 2], p1.y + pb2[ab + 3]);
        o[1] = make_float4(p2.x + pb2[ab + 4], p2.y + pb2[ab + 5],
                           p3.x + pb2[ab + 6], p3.y + pb2[ab + 7]);
    }

    float vpart = 0.f;
    for (int jc = 0; jc < 8; jc++) {
        __syncthreads();
        for (int i = tid; i < 2048; i += 256) {
            int k = i >> 6, c = i & 63;
            sW1[i] = vW1[k * P_DIM + jc * 64 + c];
        }
        if (tid < 64) sv2[tid] = vW2[jc * 64 + tid];
        __syncthreads();

        int jb = jc * 64 + oct * 8;
        unsigned long long u0 = pack2(vb1[jb + 0], vb1[jb + 1]);
        unsigned long long u1 = pack2(vb1[jb + 2], vb1[jb + 3]);
        unsigned long long u2 = pack2(vb1[jb + 4], vb1[jb + 5]);
        unsigned long long u3 = pack2(vb1[jb + 6], vb1[jb + 7]);
#pragma unroll
        for (int k = 0; k < 32; k++) {
            unsigned long long hk = pack2(hreg[k], hreg[k]);
            const ulonglong2* w = (const ulonglong2*)&sW1[k * 64 + oct * 8];
            ulonglong2 wa = w[0], wb = w[1];
            fma2(u0, hk, wa.x); fma2(u1, hk, wa.y);
            fma2(u2, hk, wb.x); fma2(u3, hk, wb.y);
        }
        float2 a0 = unpack2(u0), a1 = unpack2(u1), a2 = unpack2(u2), a3 = unpack2(u3);
        const float* s2 = &sv2[oct * 8];
        vpart += fmaxf(a0.x, 0.f) * s2[0] + fmaxf(a0.y, 0.f) * s2[1]
               + fmaxf(a1.x, 0.f) * s2[2] + fmaxf(a1.y, 0.f) * s2[3]
               + fmaxf(a2.x, 0.f) * s2[4] + fmaxf(a2.y, 0.f) * s2[5]
               + fmaxf(a3.x, 0.f) * s2[6] + fmaxf(a3.y, 0.f) * s2[7];
    }
    vpart += __shfl_down_sync(0xffffffffu, vpart, 4);
    vpart += __shfl_down_sync(0xffffffffu, vpart, 2);
    vpart += __shfl_down_sync(0xffffffffu, vpart, 1);
    if (oct == 0) out[(long long)N_NODES * A_DIM + n] = vpart + vb2[0];
}

// ---------------- launch ----------------
extern "C" void kernel_launch(void* const* d_in, const int* in_sizes, int n_in,
                              void* d_out, int out_size) {
    const float* feat = (const float*)d_in[0];
    const int*   ei   = (const int*)d_in[1];
    const float* W1  = (const float*)d_in[2];
    const float* b1  = (const float*)d_in[3];
    const float* W2  = (const float*)d_in[4];
    const float* b2  = (const float*)d_in[5];
    const float* pW1 = (const float*)d_in[6];
    const float* pb1 = (const float*)d_in[7];
    const float* pW2 = (const float*)d_in[8];
    const float* pb2 = (const float*)d_in[9];
    const float* vW1 = (const float*)d_in[10];
    const float* vb1 = (const float*)d_in[11];
    const float* vW2 = (const float*)d_in[12];
    const float* vb2 = (const float*)d_in[13];
    float* out = (float*)d_out;

    int *p_cnt, *p_rowst, *p_cursor, *p_sums, *p_csr;
    float *p_dinv, *p_xw, *p_h;
    cudaGetSymbolAddress((void**)&p_cnt,    g_cnt);
    cudaGetSymbolAddress((void**)&p_rowst,  g_rowst);
    cudaGetSymbolAddress((void**)&p_cursor, g_cursor);
    cudaGetSymbolAddress((void**)&p_sums,   g_sums);
    cudaGetSymbolAddress((void**)&p_csr,    g_csr);
    cudaGetSymbolAddress((void**)&p_dinv,   g_dinv);
    cudaGetSymbolAddress((void**)&p_xw,     g_xw);
    cudaGetSymbolAddress((void**)&p_h,      g_h);

    const int T = 256;

    // ---- CSR build ----
    k_zeroi  <<<(N_NODES + T - 1) / T, T>>>(p_cnt, N_NODES);
    k_count  <<<(N_EDGES + T - 1) / T, T>>>(ei, p_cnt);
    k_scan1  <<<SCAN_NB, SCAN_T>>>(p_cnt, p_rowst, p_sums);
    k_scan2  <<<1, 256>>>(p_sums);
    k_scan3  <<<SCAN_NB, SCAN_T>>>(p_cnt, p_rowst, p_sums, p_cursor, p_dinv);
    k_scatter<<<(N_EDGES + T - 1) / T, T>>>(ei, p_cursor, p_csr);

    // ---- conv1 ----
    k_gemm_fw1<<<(N_NODES + 127) / 128, 128>>>(feat, W1, p_xw);
    k_aggr    <<<(N_NODES * 8 + T - 1) / T, T>>>(p_xw, p_dinv, p_cnt, p_rowst, p_csr, b1, p_h);

    // ---- conv2 ----
    k_gemm_hw2<<<(N_NODES + 127) / 128, 128>>>(p_h, W2, p_xw);
    k_aggr    <<<(N_NODES * 8 + T - 1) / T, T>>>(p_xw, p_dinv, p_cnt, p_rowst, p_csr, b2, p_h);

    // ---- heads ----
    k_head<<<N_NODES / 32, 256>>>(p_h, pW1, pb1, pW2, pb2, vW1, vb1, vW2, vb2, out);
}

// round 8
// speedup vs baseline: 2.9789x; 2.8265x over previous
#include <cuda_runtime.h>
#include <cstdint>

#define N_NODES 100000
#define N_EDGES 1600000
#define F_IN    256
#define H_DIM   32
#define P_DIM   512
#define A_DIM   64

#define SCAN_T  512
#define SCAN_NB 196   // 196*512 = 100352 >= N_NODES

// ---------------- scratch (static __device__, allocation-free) ----------------
__device__ int   g_cnt   [N_NODES];
__device__ int   g_rowst [N_NODES];
__device__ int   g_cursor[N_NODES];
__device__ int   g_sums  [SCAN_T];
__device__ int   g_csr   [N_EDGES];
__device__ float g_dinv  [N_NODES];
__device__ float g_xw    [N_NODES * H_DIM];
__device__ float g_h     [N_NODES * H_DIM];

// ---------------- packed f32x2 helpers ----------------
__device__ __forceinline__ unsigned long long pack2(float x, float y) {
    unsigned long long r;
    asm("mov.b64 %0, {%1, %2};" : "=l"(r) : "f"(x), "f"(y));
    return r;
}
__device__ __forceinline__ void fma2(unsigned long long& d, unsigned long long a, unsigned long long b) {
    asm("fma.rn.f32x2 %0, %1, %2, %0;" : "+l"(d) : "l"(a), "l"(b));
}
__device__ __forceinline__ float2 unpack2(unsigned long long v) {
    float2 f;
    asm("mov.b64 {%0, %1}, %2;" : "=f"(f.x), "=f"(f.y) : "l"(v));
    return f;
}

// ================= CSR build =================
__global__ void k_zeroi(int* __restrict__ p, int n) {
    int i = blockIdx.x * blockDim.x + threadIdx.x;
    if (i < n) p[i] = 0;
}

__global__ void k_count(const int* __restrict__ ei, int* __restrict__ cnt) {
    int e = blockIdx.x * blockDim.x + threadIdx.x;
    if (e < N_EDGES) atomicAdd(&cnt[__ldg(&ei[N_EDGES + e])], 1);
}

__global__ void k_scan1(const int* __restrict__ cnt, int* __restrict__ incl,
                        int* __restrict__ sums) {
    __shared__ int s[SCAN_T];
    int t = threadIdx.x;
    int i = blockIdx.x * SCAN_T + t;
    int v = (i < N_NODES) ? cnt[i] : 0;
    s[t] = v;
    __syncthreads();
#pragma unroll
    for (int off = 1; off < SCAN_T; off <<= 1) {
        int a = (t >= off) ? s[t - off] : 0;
        __syncthreads();
        s[t] += a;
        __syncthreads();
    }
    if (i < N_NODES) incl[i] = s[t];
    if (t == SCAN_T - 1) sums[blockIdx.x] = s[t];
}

__global__ void k_scan2(int* __restrict__ sums) {
    __shared__ int s[256];
    int t = threadIdx.x;
    int v = (t < SCAN_NB) ? sums[t] : 0;
    s[t] = v;
    __syncthreads();
#pragma unroll
    for (int off = 1; off < 256; off <<= 1) {
        int a = (t >= off) ? s[t - off] : 0;
        __syncthreads();
        s[t] += a;
        __syncthreads();
    }
    sums[t] = s[t] - v;   // exclusive
}

__global__ void k_scan3(const int* __restrict__ cnt, int* __restrict__ rowst,
                        const int* __restrict__ sums, int* __restrict__ cursor,
                        float* __restrict__ dinv) {
    int t = threadIdx.x;
    int i = blockIdx.x * SCAN_T + t;
    if (i < N_NODES) {
        int c = cnt[i];
        int excl = rowst[i] - c + sums[blockIdx.x];
        rowst[i]  = excl;
        cursor[i] = excl;
        dinv[i]   = rsqrtf((float)c + 1.0f);
    }
}

__global__ void k_scatter(const int* __restrict__ ei, int* __restrict__ cursor,
                          int* __restrict__ csr) {
    int e = blockIdx.x * blockDim.x + threadIdx.x;
    if (e < N_EDGES) {
        int dst = __ldg(&ei[N_EDGES + e]);
        int pos = atomicAdd(&cursor[dst], 1);
        csr[pos] = __ldg(&ei[e]);
    }
}

// ================= CSR aggregation (atomic-free, fused finish) =================
__global__ __launch_bounds__(256) void k_aggr(const float* __restrict__ xw,
                                              const float* __restrict__ dinv,
                                              const int* __restrict__ cnt,
                                              const int* __restrict__ rowst,
                                              const int* __restrict__ csr,
                                              const float* __restrict__ b,
                                              float* __restrict__ out) {
    int idx = blockIdx.x * blockDim.x + threadIdx.x;
    int n = idx >> 3;
    int q = idx & 7;
    if (n >= N_NODES) return;

    int start = __ldg(&rowst[n]);
    int deg   = __ldg(&cnt[n]);
    float4 acc = make_float4(0.f, 0.f, 0.f, 0.f);

    int src_n = (deg > 0) ? __ldg(&csr[start]) : 0;
    for (int j = 0; j < deg; j++) {
        int src = src_n;
        if (j + 1 < deg) src_n = __ldg(&csr[start + j + 1]);
        float ds = __ldg(&dinv[src]);
        float4 v = __ldg(&((const float4*)xw)[src * 8 + q]);
        acc.x = fmaf(v.x, ds, acc.x);
        acc.y = fmaf(v.y, ds, acc.y);
        acc.z = fmaf(v.z, ds, acc.z);
        acc.w = fmaf(v.w, ds, acc.w);
    }
    float dd  = __ldg(&dinv[n]);
    float dd2 = dd * dd;
    float4 sv = __ldg(&((const float4*)xw)[n * 8 + q]);
    float4 bb = __ldg(&((const float4*)b)[q]);
    float4 r;
    r.x = fmaxf(fmaf(acc.x, dd, fmaf(sv.x, dd2, bb.x)), 0.f);
    r.y = fmaxf(fmaf(acc.y, dd, fmaf(sv.y, dd2, bb.y)), 0.f);
    r.z = fmaxf(fmaf(acc.z, dd, fmaf(sv.z, dd2, bb.z)), 0.f);
    r.w = fmaxf(fmaf(acc.w, dd, fmaf(sv.w, dd2, bb.w)), 0.f);
    ((float4*)out)[n * 8 + q] = r;
}

// ================= GEMM1 (R3 tiled, measured 131us) =================
__global__ __launch_bounds__(128) void k_gemm_fw1(const float* __restrict__ feat,
                                                  const float* __restrict__ W1,
                                                  float* __restrict__ out) {
    __shared__ float sW[64 * 32];
    __shared__ float sF[128 * 65];
    int tid  = threadIdx.x;
    int base = blockIdx.x * 128;
    int n    = base + tid;

    float acc[32];
#pragma unroll
    for (int h = 0; h < 32; h++) acc[h] = 0.f;

    for (int kc = 0; kc < 4; kc++) {
        __syncthreads();
        for (int i = tid; i < 64 * 32; i += 128) sW[i] = W1[kc * 2048 + i];
        for (int i = tid; i < 128 * 64; i += 128) {
            int r = i >> 6, c = i & 63;
            int nn = base + r;
            sF[r * 65 + c] = (nn < N_NODES) ? feat[(long long)nn * F_IN + kc * 64 + c] : 0.f;
        }
        __syncthreads();
#pragma unroll 4
        for (int k = 0; k < 64; k++) {
            float f = sF[tid * 65 + k];
            const float4* w4 = (const float4*)&sW[k * 32];
#pragma unroll
            for (int h4 = 0; h4 < 8; h4++) {
                float4 w = w4[h4];
                acc[h4 * 4 + 0] += f * w.x;
                acc[h4 * 4 + 1] += f * w.y;
                acc[h4 * 4 + 2] += f * w.z;
                acc[h4 * 4 + 3] += f * w.w;
            }
        }
    }
    if (n < N_NODES) {
        float4* o = (float4*)(out + (long long)n * H_DIM);
#pragma unroll
        for (int h4 = 0; h4 < 8; h4++)
            o[h4] = make_float4(acc[h4 * 4], acc[h4 * 4 + 1], acc[h4 * 4 + 2], acc[h4 * 4 + 3]);
    }
}

// ================= GEMM2 (R3 tiled) =================
__global__ __launch_bounds__(128) void k_gemm_hw2(const float* __restrict__ hin,
                                                  const float* __restrict__ W2,
                                                  float* __restrict__ out) {
    __shared__ float sW[32 * 32];
    __shared__ float sH[128 * 33];
    int tid  = threadIdx.x;
    int base = blockIdx.x * 128;
    int n    = base + tid;

    for (int i = tid; i < 1024; i += 128) sW[i] = W2[i];
    for (int i = tid; i < 128 * 32; i += 128) {
        int r = i >> 5, c = i & 31;
        int nn = base + r;
        sH[r * 33 + c] = (nn < N_NODES) ? hin[(long long)nn * H_DIM + c] : 0.f;
    }
    __syncthreads();

    float acc[32];
#pragma unroll
    for (int h = 0; h < 32; h++) acc[h] = 0.f;
#pragma unroll 4
    for (int k = 0; k < 32; k++) {
        float f = sH[tid * 33 + k];
        const float4* w4 = (const float4*)&sW[k * 32];
#pragma unroll
        for (int h4 = 0; h4 < 8; h4++) {
            float4 w = w4[h4];
            acc[h4 * 4 + 0] += f * w.x;
            acc[h4 * 4 + 1] += f * w.y;
            acc[h4 * 4 + 2] += f * w.z;
            acc[h4 * 4 + 3] += f * w.w;
        }
    }
    if (n < N_NODES) {
        float4* o = (float4*)(out + (long long)n * H_DIM);
#pragma unroll
        for (int h4 = 0; h4 < 8; h4++)
            o[h4] = make_float4(acc[h4 * 4], acc[h4 * 4 + 1], acc[h4 * 4 + 2], acc[h4 * 4 + 3]);
    }
}

// ================= fused MLP heads (v2: uniform weights + node-pair tiling) =================
// Block: 64 nodes, 256 threads (8 warps).
// warp = output-octet (uniform smem weight address -> broadcast LDS),
// lane = node pair (2 nodes per thread, f32x2 packed across nodes).
__global__ __launch_bounds__(256, 2) void k_head(const float* __restrict__ h,
    const float* __restrict__ pW1, const float* __restrict__ pb1,
    const float* __restrict__ pW2, const float* __restrict__ pb2,
    const float* __restrict__ vW1, const float* __restrict__ vb1,
    const float* __restrict__ vW2, const float* __restrict__ vb2,
    float* __restrict__ out)
{
    __shared__ __align__(16) float  sh2 [32 * 64];   // 8 KB : [k][node]
    __shared__ __align__(16) float  sW1 [32 * 64];   // 8 KB : [k][j-local]
    __shared__ __align__(16) float  sW2u[64 * 64];   // 16 KB: [j-local][a] (policy) / sv2+sred (value)
    __shared__ __align__(16) float2 su2 [64 * 32];   // 16 KB: [j-local][pair]
    // total: exactly 48 KB

    float*  sv2  = sW2u;                 // 64 floats (value layer-2 weights)
    float2* sred = (float2*)(sW2u + 64); // 8*32 float2 (value cross-warp partials)

    int tid  = threadIdx.x;
    int wid  = tid >> 5;
    int lane = tid & 31;
    int base = blockIdx.x * 64;
    int n0   = base + 2 * lane;
    int n1   = n0 + 1;

    // stage h transposed + node-pair packed: sh2[k*64 + node] = h[node][k]
    for (int i = tid; i < 2048; i += 256) {
        int k = i >> 6, node = i & 63;
        int nn = min(base + node, N_NODES - 1);
        sh2[k * 64 + node] = __ldg(&h[nn * H_DIM + k]);
    }

    unsigned long long pacc0[4], pacc1[4];
#pragma unroll
    for (int p = 0; p < 4; p++) { pacc0[p] = 0ull; pacc1[p] = 0ull; }

    // ================= policy =================
    for (int jc = 0; jc < 8; jc++) {
        __syncthreads();
        {   // sW1[k][c] = pW1[k][jc*64 + c]
            const float4* src = (const float4*)pW1;
            for (int i = tid; i < 512; i += 256) {
                int k = i >> 4, c4 = i & 15;
                ((float4*)sW1)[i] = __ldg(&src[k * (P_DIM / 4) + jc * 16 + c4]);
            }
            // sW2u[j][a] = pW2[jc*64 + j][a]  (contiguous)
            const float4* src2 = (const float4*)pW2;
            for (int i = tid; i < 1024; i += 256)
                ((float4*)sW2u)[i] = __ldg(&src2[jc * 1024 + i]);
        }
        __syncthreads();

        int jb = jc * 64 + wid * 8;
        unsigned long long u0[4], u1[4];
#pragma unroll
        for (int p = 0; p < 4; p++) {
            u0[p] = pack2(__ldg(&pb1[jb + 2 * p]), __ldg(&pb1[jb + 2 * p + 1]));
            u1[p] = u0[p];
        }
        // layer 1: u[n][8] += h[n][k] * W1[k][8]   (weights broadcast, h node-pair packed)
#pragma unroll 8
        for (int k = 0; k < 32; k++) {
            float2 hh = *(const float2*)&sh2[k * 64 + 2 * lane];
            unsigned long long h0 = pack2(hh.x, hh.x);
            unsigned long long h1 = pack2(hh.y, hh.y);
            const ulonglong2* wr = (const ulonglong2*)&sW1[k * 64 + wid * 8];
            ulonglong2 wa = wr[0], wb = wr[1];
            fma2(u0[0], h0, wa.x); fma2(u0[1], h0, wa.y);
            fma2(u0[2], h0, wb.x); fma2(u0[3], h0, wb.y);
            fma2(u1[0], h1, wa.x); fma2(u1[1], h1, wa.y);
            fma2(u1[2], h1, wb.x); fma2(u1[3], h1, wb.y);
        }
        // relu + transpose to [j][pair]
#pragma unroll
        for (int p = 0; p < 4; p++) {
            float2 a = unpack2(u0[p]);
            float2 b = unpack2(u1[p]);
            su2[(wid * 8 + 2 * p)     * 32 + lane] = make_float2(fmaxf(a.x, 0.f), fmaxf(b.x, 0.f));
            su2[(wid * 8 + 2 * p + 1) * 32 + lane] = make_float2(fmaxf(a.y, 0.f), fmaxf(b.y, 0.f));
        }
        __syncthreads();
        // layer 2: pacc[n][8] += u[n][j] * W2[j][8]
#pragma unroll 4
        for (int j = 0; j < 64; j++) {
            float2 uu = su2[j * 32 + lane];
            unsigned long long us0 = pack2(uu.x, uu.x);
            unsigned long long us1 = pack2(uu.y, uu.y);
            const ulonglong2* wr = (const ulonglong2*)&sW2u[j * 64 + wid * 8];
            ulonglong2 wa = wr[0], wb = wr[1];
            fma2(pacc0[0], us0, wa.x); fma2(pacc0[1], us0, wa.y);
            fma2(pacc0[2], us0, wb.x); fma2(pacc0[3], us0, wb.y);
            fma2(pacc1[0], us1, wa.x); fma2(pacc1[1], us1, wa.y);
            fma2(pacc1[2], us1, wb.x); fma2(pacc1[3], us1, wb.y);
        }
    }
    // write policy (cols wid*8 .. wid*8+7)
    {
        int ab = wid * 8;
        float bb[8];
#pragma unroll
        for (int p = 0; p < 8; p++) bb[p] = __ldg(&pb2[ab + p]);
        float2 q0 = unpack2(pacc0[0]), q1 = unpack2(pacc0[1]);
        float2 q2 = unpack2(pacc0[2]), q3 = unpack2(pacc0[3]);
        if (n0 < N_NODES) {
            float4* o = (float4*)(out + (long long)n0 * A_DIM + ab);
            o[0] = make_float4(q0.x + bb[0], q0.y + bb[1], q1.x + bb[2], q1.y + bb[3]);
            o[1] = make_float4(q2.x + bb[4], q2.y + bb[5], q3.x + bb[6], q3.y + bb[7]);
        }
        float2 r0 = unpack2(pacc1[0]), r1 = unpack2(pacc1[1]);
        float2 r2 = unpack2(pacc1[2]), r3 = unpack2(pacc1[3]);
        if (n1 < N_NODES) {
            float4* o = (float4*)(out + (long long)n1 * A_DIM + ab);
            o[0] = make_float4(r0.x + bb[0], r0.y + bb[1], r1.x + bb[2], r1.y + bb[3]);
            o[1] = make_float4(r2.x + bb[4], r2.y + bb[5], r3.x + bb[6], r3.y + bb[7]);
        }
    }

    // ================= value =================
    float v0 = 0.f, v1 = 0.f;
    for (int jc = 0; jc < 8; jc++) {
        __syncthreads();
        {
            const float4* src = (const float4*)vW1;
            for (int i = tid; i < 512; i += 256) {
                int k = i >> 4, c4 = i & 15;
                ((float4*)sW1)[i] = __ldg(&src[k * (P_DIM / 4) + jc * 16 + c4]);
            }
            if (tid < 64) sv2[tid] = __ldg(&vW2[jc * 64 + tid]);
        }
        __syncthreads();

        int jb = jc * 64 + wid * 8;
        unsigned long long u0[4], u1[4];
#pragma unroll
        for (int p = 0; p < 4; p++) {
            u0[p] = pack2(__ldg(&vb1[jb + 2 * p]), __ldg(&vb1[jb + 2 * p + 1]));
            u1[p] = u0[p];
        }
#pragma unroll 8
        for (int k = 0; k < 32; k++) {
            float2 hh = *(const float2*)&sh2[k * 64 + 2 * lane];
            unsigned long long h0 = pack2(hh.x, hh.x);
            unsigned long long h1 = pack2(hh.y, hh.y);
            const ulonglong2* wr = (const ulonglong2*)&sW1[k * 64 + wid * 8];
            ulonglong2 wa = wr[0], wb = wr[1];
            fma2(u0[0], h0, wa.x); fma2(u0[1], h0, wa.y);
            fma2(u0[2], h0, wb.x); fma2(u0[3], h0, wb.y);
            fma2(u1[0], h1, wa.x); fma2(u1[1], h1, wa.y);
            fma2(u1[2], h1, wb.x); fma2(u1[3], h1, wb.y);
        }
#pragma unroll
        for (int p = 0; p < 4; p++) {
            float w0 = sv2[wid * 8 + 2 * p];
            float w1 = sv2[wid * 8 + 2 * p + 1];
            float2 a = unpack2(u0[p]);
            float2 b = unpack2(u1[p]);
            v0 = fmaf(fmaxf(a.x, 0.f), w0, fmaf(fmaxf(a.y, 0.f), w1, v0));
            v1 = fmaf(fmaxf(b.x, 0.f), w0, fmaf(fmaxf(b.y, 0.f), w1, v1));
        }
    }
    sred[wid * 32 + lane] = make_float2(v0, v1);
    __syncthreads();
    if (wid == 0) {
        float s0 = 0.f, s1 = 0.f;
#pragma unroll
        for (int w = 0; w < 8; w++) {
            float2 t = sred[w * 32 + lane];
            s0 += t.x; s1 += t.y;
        }
        float vb = __ldg(&vb2[0]);
        if (n0 < N_NODES) out[(long long)N_NODES * A_DIM + n0] = s0 + vb;
        if (n1 < N_NODES) out[(long long)N_NODES * A_DIM + n1] = s1 + vb;
    }
}

// ---------------- launch ----------------
extern "C" void kernel_launch(void* const* d_in, const int* in_sizes, int n_in,
                              void* d_out, int out_size) {
    const float* feat = (const float*)d_in[0];
    const int*   ei   = (const int*)d_in[1];
    const float* W1  = (const float*)d_in[2];
    const float* b1  = (const float*)d_in[3];
    const float* W2  = (const float*)d_in[4];
    const float* b2  = (const float*)d_in[5];
    const float* pW1 = (const float*)d_in[6];
    const float* pb1 = (const float*)d_in[7];
    const float* pW2 = (const float*)d_in[8];
    const float* pb2 = (const float*)d_in[9];
    const float* vW1 = (const float*)d_in[10];
    const float* vb1 = (const float*)d_in[11];
    const float* vW2 = (const float*)d_in[12];
    const float* vb2 = (const float*)d_in[13];
    float* out = (float*)d_out;

    int *p_cnt, *p_rowst, *p_cursor, *p_sums, *p_csr;
    float *p_dinv, *p_xw, *p_h;
    cudaGetSymbolAddress((void**)&p_cnt,    g_cnt);
    cudaGetSymbolAddress((void**)&p_rowst,  g_rowst);
    cudaGetSymbolAddress((void**)&p_cursor, g_cursor);
    cudaGetSymbolAddress((void**)&p_sums,   g_sums);
    cudaGetSymbolAddress((void**)&p_csr,    g_csr);
    cudaGetSymbolAddress((void**)&p_dinv,   g_dinv);
    cudaGetSymbolAddress((void**)&p_xw,     g_xw);
    cudaGetSymbolAddress((void**)&p_h,      g_h);

    const int T = 256;

    // ---- CSR build ----
    k_zeroi  <<<(N_NODES + T - 1) / T, T>>>(p_cnt, N_NODES);
    k_count  <<<(N_EDGES + T - 1) / T, T>>>(ei, p_cnt);
    k_scan1  <<<SCAN_NB, SCAN_T>>>(p_cnt, p_rowst, p_sums);
    k_scan2  <<<1, 256>>>(p_sums);
    k_scan3  <<<SCAN_NB, SCAN_T>>>(p_cnt, p_rowst, p_sums, p_cursor, p_dinv);
    k_scatter<<<(N_EDGES + T - 1) / T, T>>>(ei, p_cursor, p_csr);

    // ---- conv1 ----
    k_gemm_fw1<<<(N_NODES + 127) / 128, 128>>>(feat, W1, p_xw);
    k_aggr    <<<(N_NODES * 8 + T - 1) / T, T>>>(p_xw, p_dinv, p_cnt, p_rowst, p_csr, b1, p_h);

    // ---- conv2 ----
    k_gemm_hw2<<<(N_NODES + 127) / 128, 128>>>(p_h, W2, p_xw);
    k_aggr    <<<(N_NODES * 8 + T - 1) / T, T>>>(p_xw, p_dinv, p_cnt, p_rowst, p_csr, b2, p_h);

    // ---- heads ----
    k_head<<<(N_NODES + 63) / 64, 256>>>(p_h, pW1, pb1, pW2, pb2, vW1, vb1, vW2, vb2, out);
}

// round 10
// speedup vs baseline: 3.2735x; 1.0989x over previous
#include <cuda_runtime.h>
#include <cstdint>

#define N_NODES 100000
#define N_EDGES 1600000
#define F_IN    256
#define H_DIM   32
#define P_DIM   512
#define A_DIM   64

#define SCAN_T  512
#define SCAN_NB 196   // 196*512 = 100352 >= N_NODES

// fw1 pipeline geometry
#define FW1_KC      32                      // k-chunk
#define FW1_NCHUNK  (F_IN / FW1_KC)         // 8
#define FW1_PAD     33                      // odd -> conflict-free row reads
#define FW1_TILEF   (128 * FW1_PAD)         // floats per F buffer (4224)
#define FW1_SMEMF   (F_IN * H_DIM + 2 * FW1_TILEF)   // 8192 + 8448 = 16640 floats (66.56 KB)

// ---------------- scratch (static __device__, allocation-free) ----------------
__device__ int   g_cnt   [N_NODES];
__device__ int   g_rowst [N_NODES];
__device__ int   g_cursor[N_NODES];
__device__ int   g_sums  [SCAN_T];
__device__ int   g_csr   [N_EDGES];
__device__ float g_dinv  [N_NODES];
__device__ float g_xw    [N_NODES * H_DIM];
__device__ float g_h     [N_NODES * H_DIM];

// ---------------- packed f32x2 helpers ----------------
__device__ __forceinline__ unsigned long long pack2(float x, float y) {
    unsigned long long r;
    asm("mov.b64 %0, {%1, %2};" : "=l"(r) : "f"(x), "f"(y));
    return r;
}
__device__ __forceinline__ void fma2(unsigned long long& d, unsigned long long a, unsigned long long b) {
    asm("fma.rn.f32x2 %0, %1, %2, %0;" : "+l"(d) : "l"(a), "l"(b));
}
__device__ __forceinline__ float2 unpack2(unsigned long long v) {
    float2 f;
    asm("mov.b64 {%0, %1}, %2;" : "=f"(f.x), "=f"(f.y) : "l"(v));
    return f;
}

// ---------------- cp.async helpers ----------------
__device__ __forceinline__ void cpa4(float* dst_smem, const float* src) {
    uint32_t d = (uint32_t)__cvta_generic_to_shared(dst_smem);
    asm volatile("cp.async.ca.shared.global [%0], [%1], 4;" :: "r"(d), "l"(src) : "memory");
}
__device__ __forceinline__ void cp_commit() {
    asm volatile("cp.async.commit_group;" ::: "memory");
}
template<int N>
__device__ __forceinline__ void cp_wait() {
    asm volatile("cp.async.wait_group %0;" :: "n"(N) : "memory");
}

// ================= CSR build =================
__global__ void k_zeroi(int* __restrict__ p, int n) {
    int i = blockIdx.x * blockDim.x + threadIdx.x;
    if (i < n) p[i] = 0;
}

__global__ void k_count(const int* __restrict__ ei, int* __restrict__ cnt) {
    int e = blockIdx.x * blockDim.x + threadIdx.x;
    if (e < N_EDGES) atomicAdd(&cnt[__ldg(&ei[N_EDGES + e])], 1);
}

__global__ void k_scan1(const int* __restrict__ cnt, int* __restrict__ incl,
                        int* __restrict__ sums) {
    __shared__ int s[SCAN_T];
    int t = threadIdx.x;
    int i = blockIdx.x * SCAN_T + t;
    int v = (i < N_NODES) ? cnt[i] : 0;
    s[t] = v;
    __syncthreads();
#pragma unroll
    for (int off = 1; off < SCAN_T; off <<= 1) {
        int a = (t >= off) ? s[t - off] : 0;
        __syncthreads();
        s[t] += a;
        __syncthreads();
    }
    if (i < N_NODES) incl[i] = s[t];
    if (t == SCAN_T - 1) sums[blockIdx.x] = s[t];
}

__global__ void k_scan2(int* __restrict__ sums) {
    __shared__ int s[256];
    int t = threadIdx.x;
    int v = (t < SCAN_NB) ? sums[t] : 0;
    s[t] = v;
    __syncthreads();
#pragma unroll
    for (int off = 1; off < 256; off <<= 1) {
        int a = (t >= off) ? s[t - off] : 0;
        __syncthreads();
        s[t] += a;
        __syncthreads();
    }
    sums[t] = s[t] - v;   // exclusive
}

__global__ void k_scan3(const int* __restrict__ cnt, int* __restrict__ rowst,
                        const int* __restrict__ sums, int* __restrict__ cursor,
                        float* __restrict__ dinv) {
    int t = threadIdx.x;
    int i = blockIdx.x * SCAN_T + t;
    if (i < N_NODES) {
        int c = cnt[i];
        int excl = rowst[i] - c + sums[blockIdx.x];
        rowst[i]  = excl;
        cursor[i] = excl;
        dinv[i]   = rsqrtf((float)c + 1.0f);
    }
}

__global__ void k_scatter(const int* __restrict__ ei, int* __restrict__ cursor,
                          int* __restrict__ csr) {
    int e = blockIdx.x * blockDim.x + threadIdx.x;
    if (e < N_EDGES) {
        int dst = __ldg(&ei[N_EDGES + e]);
        int pos = atomicAdd(&cursor[dst], 1);
        csr[pos] = __ldg(&ei[e]);
    }
}

// ================= CSR aggregation (atomic-free, fused finish) =================
__global__ __launch_bounds__(256) void k_aggr(const float* __restrict__ xw,
                                              const float* __restrict__ dinv,
                                              const int* __restrict__ cnt,
                                              const int* __restrict__ rowst,
                                              const int* __restrict__ csr,
                                              const float* __restrict__ b,
                                              float* __restrict__ out) {
    int idx = blockIdx.x * blockDim.x + threadIdx.x;
    int n = idx >> 3;
    int q = idx & 7;
    if (n >= N_NODES) return;

    int start = __ldg(&rowst[n]);
    int deg   = __ldg(&cnt[n]);
    float4 acc = make_float4(0.f, 0.f, 0.f, 0.f);

    int src_n = (deg > 0) ? __ldg(&csr[start]) : 0;
    for (int j = 0; j < deg; j++) {
        int src = src_n;
        if (j + 1 < deg) src_n = __ldg(&csr[start + j + 1]);
        float ds = __ldg(&dinv[src]);
        float4 v = __ldg(&((const float4*)xw)[src * 8 + q]);
        acc.x = fmaf(v.x, ds, acc.x);
        acc.y = fmaf(v.y, ds, acc.y);
        acc.z = fmaf(v.z, ds, acc.z);
        acc.w = fmaf(v.w, ds, acc.w);
    }
    float dd  = __ldg(&dinv[n]);
    float dd2 = dd * dd;
    float4 sv = __ldg(&((const float4*)xw)[n * 8 + q]);
    float4 bb = __ldg(&((const float4*)b)[q]);
    float4 r;
    r.x = fmaxf(fmaf(acc.x, dd, fmaf(sv.x, dd2, bb.x)), 0.f);
    r.y = fmaxf(fmaf(acc.y, dd, fmaf(sv.y, dd2, bb.y)), 0.f);
    r.z = fmaxf(fmaf(acc.z, dd, fmaf(sv.z, dd2, bb.z)), 0.f);
    r.w = fmaxf(fmaf(acc.w, dd, fmaf(sv.w, dd2, bb.w)), 0.f);
    ((float4*)out)[n * 8 + q] = r;
}

// ================= GEMM1: cp.async pipelined, f32x2 =================
__global__ __launch_bounds__(128) void k_gemm_fw1(const float* __restrict__ feat,
                                                  const float* __restrict__ W1,
                                                  float* __restrict__ out) {
    extern __shared__ float smem[];
    float* sW  = smem;                     // 8192 floats
    float* sF0 = smem + F_IN * H_DIM;      // 4224 floats
    float* sF1 = sF0 + FW1_TILEF;          // 4224 floats

    int tid  = threadIdx.x;
    int base = blockIdx.x * 128;

    auto stage = [&](int c, float* buf) {
#pragma unroll
        for (int i = tid; i < 128 * FW1_KC; i += 128) {
            int r  = i >> 5;          // row 0..127
            int kk = i & 31;          // k within chunk
            int nn = min(base + r, N_NODES - 1);
            cpa4(&buf[r * FW1_PAD + kk], &feat[(long long)nn * F_IN + c * FW1_KC + kk]);
        }
    };

    stage(0, sF0); cp_commit();
    stage(1, sF1); cp_commit();

    for (int i = tid; i < (F_IN * H_DIM) / 4; i += 128)
        ((float4*)sW)[i] = __ldg(&((const float4*)W1)[i]);

    unsigned long long acc[16];
#pragma unroll
    for (int i = 0; i < 16; i++) acc[i] = 0ull;

    for (int c = 0; c < FW1_NCHUNK; c++) {
        if (c == FW1_NCHUNK - 1) cp_wait<0>(); else cp_wait<1>();
        __syncthreads();
        const float* sF = (c & 1) ? sF1 : sF0;
#pragma unroll 8
        for (int k = 0; k < FW1_KC; k++) {
            float f = sF[tid * FW1_PAD + k];
            unsigned long long hk = pack2(f, f);
            const ulonglong2* w = (const ulonglong2*)&sW[(c * FW1_KC + k) * H_DIM];
#pragma unroll
            for (int p = 0; p < 8; p++) {
                ulonglong2 ww = w[p];
                fma2(acc[p * 2 + 0], hk, ww.x);
                fma2(acc[p * 2 + 1], hk, ww.y);
            }
        }
        __syncthreads();
        if (c + 2 < FW1_NCHUNK) {
            stage(c + 2, (c & 1) ? sF1 : sF0);
            cp_commit();
        }
    }

    int n = base + tid;
    if (n < N_NODES) {
        float4* o = (float4*)(out + (long long)n * H_DIM);
#pragma unroll
        for (int p = 0; p < 8; p++) {
            float2 a = unpack2(acc[p * 2]), c2 = unpack2(acc[p * 2 + 1]);
            o[p] = make_float4(a.x, a.y, c2.x, c2.y);
        }
    }
}

// ================= GEMM2: h[N,32] @ W2[32,32], W-stationary f32x2 =================
__global__ __launch_bounds__(256) void k_gemm_hw2(const float* __restrict__ hin,
                                                  const float* __restrict__ W2,
                                                  float* __restrict__ out) {
    __shared__ float sW[H_DIM * H_DIM];    // 4 KB
    int tid = threadIdx.x;
    for (int i = tid; i < H_DIM * H_DIM; i += 256) sW[i] = W2[i];
    __syncthreads();

    int n = blockIdx.x * 256 + tid;
    if (n >= N_NODES) return;

    const float4* fr = (const float4*)(hin + (long long)n * H_DIM);
    unsigned long long acc[16];
#pragma unroll
    for (int i = 0; i < 16; i++) acc[i] = 0ull;

#pragma unroll
    for (int k4 = 0; k4 < H_DIM / 4; k4++) {
        float4 f = __ldg(&fr[k4]);
        float fv[4] = {f.x, f.y, f.z, f.w};
#pragma unroll
        for (int s = 0; s < 4; s++) {
            int k = k4 * 4 + s;
            unsigned long long hk = pack2(fv[s], fv[s]);
            const ulonglong2* w = (const ulonglong2*)&sW[k * H_DIM];
#pragma unroll
            for (int p = 0; p < 8; p++) {
                ulonglong2 ww = w[p];
                fma2(acc[p * 2 + 0], hk, ww.x);
                fma2(acc[p * 2 + 1], hk, ww.y);
            }
        }
    }
    float4* o = (float4*)(out + (long long)n * H_DIM);
#pragma unroll
    for (int p = 0; p < 8; p++) {
        float2 a = unpack2(acc[p * 2]), c = unpack2(acc[p * 2 + 1]);
        o[p] = make_float4(a.x, a.y, c.x, c.y);
    }
}

// ================= fused MLP heads (v2, unchanged from passing R8) =================
__global__ __launch_bounds__(256, 2) void k_head(const float* __restrict__ h,
    const float* __restrict__ pW1, const float* __restrict__ pb1,
    const float* __restrict__ pW2, const float* __restrict__ pb2,
    const float* __restrict__ vW1, const float* __restrict__ vb1,
    const float* __restrict__ vW2, const float* __restrict__ vb2,
    float* __restrict__ out)
{
    __shared__ __align__(16) float  sh2 [32 * 64];
    __shared__ __align__(16) float  sW1 [32 * 64];
    __shared__ __align__(16) float  sW2u[64 * 64];
    __shared__ __align__(16) float2 su2 [64 * 32];

    float*  sv2  = sW2u;
    float2* sred = (float2*)(sW2u + 64);

    int tid  = threadIdx.x;
    int wid  = tid >> 5;
    int lane = tid & 31;
    int base = blockIdx.x * 64;
    int n0   = base + 2 * lane;
    int n1   = n0 + 1;

    for (int i = tid; i < 2048; i += 256) {
        int k = i >> 6, node = i & 63;
        int nn = min(base + node, N_NODES - 1);
        sh2[k * 64 + node] = __ldg(&h[nn * H_DIM + k]);
    }

    unsigned long long pacc0[4], pacc1[4];
#pragma unroll
    for (int p = 0; p < 4; p++) { pacc0[p] = 0ull; pacc1[p] = 0ull; }

    // ---------- policy ----------
    for (int jc = 0; jc < 8; jc++) {
        __syncthreads();
        {
            const float4* src = (const float4*)pW1;
            for (int i = tid; i < 512; i += 256) {
                int k = i >> 4, c4 = i & 15;
                ((float4*)sW1)[i] = __ldg(&src[k * (P_DIM / 4) + jc * 16 + c4]);
            }
            const float4* src2 = (const float4*)pW2;
            for (int i = tid; i < 1024; i += 256)
                ((float4*)sW2u)[i] = __ldg(&src2[jc * 1024 + i]);
        }
        __syncthreads();

        int jb = jc * 64 + wid * 8;
        unsigned long long u0[4], u1[4];
#pragma unroll
        for (int p = 0; p < 4; p++) {
            u0[p] = pack2(__ldg(&pb1[jb + 2 * p]), __ldg(&pb1[jb + 2 * p + 1]));
            u1[p] = u0[p];
        }
#pragma unroll 8
        for (int k = 0; k < 32; k++) {
            float2 hh = *(const float2*)&sh2[k * 64 + 2 * lane];
            unsigned long long h0 = pack2(hh.x, hh.x);
            unsigned long long h1 = pack2(hh.y, hh.y);
            const ulonglong2* wr = (const ulonglong2*)&sW1[k * 64 + wid * 8];
            ulonglong2 wa = wr[0], wb = wr[1];
            fma2(u0[0], h0, wa.x); fma2(u0[1], h0, wa.y);
            fma2(u0[2], h0, wb.x); fma2(u0[3], h0, wb.y);
            fma2(u1[0], h1, wa.x); fma2(u1[1], h1, wa.y);
            fma2(u1[2], h1, wb.x); fma2(u1[3], h1, wb.y);
        }
#pragma unroll
        for (int p = 0; p < 4; p++) {
            float2 a = unpack2(u0[p]);
            float2 b = unpack2(u1[p]);
            su2[(wid * 8 + 2 * p)     * 32 + lane] = make_float2(fmaxf(a.x, 0.f), fmaxf(b.x, 0.f));
            su2[(wid * 8 + 2 * p + 1) * 32 + lane] = make_float2(fmaxf(a.y, 0.f), fmaxf(b.y, 0.f));
        }
        __syncthreads();
#pragma unroll 4
        for (int j = 0; j < 64; j++) {
            float2 uu = su2[j * 32 + lane];
            unsigned long long us0 = pack2(uu.x, uu.x);
            unsigned long long us1 = pack2(uu.y, uu.y);
            const ulonglong2* wr = (const ulonglong2*)&sW2u[j * 64 + wid * 8];
            ulonglong2 wa = wr[0], wb = wr[1];
            fma2(pacc0[0], us0, wa.x); fma2(pacc0[1], us0, wa.y);
            fma2(pacc0[2], us0, wb.x); fma2(pacc0[3], us0, wb.y);
            fma2(pacc1[0], us1, wa.x); fma2(pacc1[1], us1, wa.y);
            fma2(pacc1[2], us1, wb.x); fma2(pacc1[3], us1, wb.y);
        }
    }
    {
        int ab = wid * 8;
        float bb[8];
#pragma unroll
        for (int p = 0; p < 8; p++) bb[p] = __ldg(&pb2[ab + p]);
        float2 q0 = unpack2(pacc0[0]), q1 = unpack2(pacc0[1]);
        float2 q2 = unpack2(pacc0[2]), q3 = unpack2(pacc0[3]);
        if (n0 < N_NODES) {
            float4* o = (float4*)(out + (long long)n0 * A_DIM + ab);
            o[0] = make_float4(q0.x + bb[0], q0.y + bb[1], q1.x + bb[2], q1.y + bb[3]);
            o[1] = make_float4(q2.x + bb[4], q2.y + bb[5], q3.x + bb[6], q3.y + bb[7]);
        }
        float2 r0 = unpack2(pacc1[0]), r1 = unpack2(pacc1[1]);
        float2 r2 = unpack2(pacc1[2]), r3 = unpack2(pacc1[3]);
        if (n1 < N_NODES) {
            float4* o = (float4*)(out + (long long)n1 * A_DIM + ab);
            o[0] = make_float4(r0.x + bb[0], r0.y + bb[1], r1.x + bb[2], r1.y + bb[3]);
            o[1] = make_float4(r2.x + bb[4], r2.y + bb[5], r3.x + bb[6], r3.y + bb[7]);
        }
    }

    // ---------- value ----------
    float v0 = 0.f, v1 = 0.f;
    for (int jc = 0; jc < 8; jc++) {
        __syncthreads();
        {
            const float4* src = (const float4*)vW1;
            for (int i = tid; i < 512; i += 256) {
                int k = i >> 4, c4 = i & 15;
                ((float4*)sW1)[i] = __ldg(&src[k * (P_DIM / 4) + jc * 16 + c4]);
            }
            if (tid < 64) sv2[tid] = __ldg(&vW2[jc * 64 + tid]);
        }
        __syncthreads();

        int jb = jc * 64 + wid * 8;
        unsigned long long u0[4], u1[4];
#pragma unroll
        for (int p = 0; p < 4; p++) {
            u0[p] = pack2(__ldg(&vb1[jb + 2 * p]), __ldg(&vb1[jb + 2 * p + 1]));
            u1[p] = u0[p];
        }
#pragma unroll 8
        for (int k = 0; k < 32; k++) {
            float2 hh = *(const float2*)&sh2[k * 64 + 2 * lane];
            unsigned long long h0 = pack2(hh.x, hh.x);
            unsigned long long h1 = pack2(hh.y, hh.y);
            const ulonglong2* wr = (const ulonglong2*)&sW1[k * 64 + wid * 8];
            ulonglong2 wa = wr[0], wb = wr[1];
            fma2(u0[0], h0, wa.x); fma2(u0[1], h0, wa.y);
            fma2(u0[2], h0, wb.x); fma2(u0[3], h0, wb.y);
            fma2(u1[0], h1, wa.x); fma2(u1[1], h1, wa.y);
            fma2(u1[2], h1, wb.x); fma2(u1[3], h1, wb.y);
        }
#pragma unroll
        for (int p = 0; p < 4; p++) {
            float w0 = sv2[wid * 8 + 2 * p];
            float w1 = sv2[wid * 8 + 2 * p + 1];
            float2 a = unpack2(u0[p]);
            float2 b = unpack2(u1[p]);
            v0 = fmaf(fmaxf(a.x, 0.f), w0, fmaf(fmaxf(a.y, 0.f), w1, v0));
            v1 = fmaf(fmaxf(b.x, 0.f), w0, fmaf(fmaxf(b.y, 0.f), w1, v1));
        }
    }
    sred[wid * 32 + lane] = make_float2(v0, v1);
    __syncthreads();
    if (wid == 0) {
        float s0 = 0.f, s1 = 0.f;
#pragma unroll
        for (int w = 0; w < 8; w++) {
            float2 t = sred[w * 32 + lane];
            s0 += t.x; s1 += t.y;
        }
        float vb = __ldg(&vb2[0]);
        if (n0 < N_NODES) out[(long long)N_NODES * A_DIM + n0] = s0 + vb;
        if (n1 < N_NODES) out[(long long)N_NODES * A_DIM + n1] = s1 + vb;
    }
}

// ---------------- launch ----------------
extern "C" void kernel_launch(void* const* d_in, const int* in_sizes, int n_in,
                              void* d_out, int out_size) {
    const float* feat = (const float*)d_in[0];
    const int*   ei   = (const int*)d_in[1];
    const float* W1  = (const float*)d_in[2];
    const float* b1  = (const float*)d_in[3];
    const float* W2  = (const float*)d_in[4];
    const float* b2  = (const float*)d_in[5];
    const float* pW1 = (const float*)d_in[6];
    const float* pb1 = (const float*)d_in[7];
    const float* pW2 = (const float*)d_in[8];
    const float* pb2 = (const float*)d_in[9];
    const float* vW1 = (const float*)d_in[10];
    const float* vb1 = (const float*)d_in[11];
    const float* vW2 = (const float*)d_in[12];
    const float* vb2 = (const float*)d_in[13];
    float* out = (float*)d_out;

    int *p_cnt, *p_rowst, *p_cursor, *p_sums, *p_csr;
    float *p_dinv, *p_xw, *p_h;
    cudaGetSymbolAddress((void**)&p_cnt,    g_cnt);
    cudaGetSymbolAddress((void**)&p_rowst,  g_rowst);
    cudaGetSymbolAddress((void**)&p_cursor, g_cursor);
    cudaGetSymbolAddress((void**)&p_sums,   g_sums);
    cudaGetSymbolAddress((void**)&p_csr,    g_csr);
    cudaGetSymbolAddress((void**)&p_dinv,   g_dinv);
    cudaGetSymbolAddress((void**)&p_xw,     g_xw);
    cudaGetSymbolAddress((void**)&p_h,      g_h);

    const int T = 256;
    const int fw1_smem_bytes = FW1_SMEMF * (int)sizeof(float);   // 66560
    cudaFuncSetAttribute(k_gemm_fw1, cudaFuncAttributeMaxDynamicSharedMemorySize,
                         fw1_smem_bytes);

    // ---- CSR build ----
    k_zeroi  <<<(N_NODES + T - 1) / T, T>>>(p_cnt, N_NODES);
    k_count  <<<(N_EDGES + T - 1) / T, T>>>(ei, p_cnt);
    k_scan1  <<<SCAN_NB, SCAN_T>>>(p_cnt, p_rowst, p_sums);
    k_scan2  <<<1, 256>>>(p_sums);
    k_scan3  <<<SCAN_NB, SCAN_T>>>(p_cnt, p_rowst, p_sums, p_cursor, p_dinv);
    k_scatter<<<(N_EDGES + T - 1) / T, T>>>(ei, p_cursor, p_csr);

    // ---- conv1 ----
    k_gemm_fw1<<<(N_NODES + 127) / 128, 128, fw1_smem_bytes>>>(feat, W1, p_xw);
    k_aggr    <<<(N_NODES * 8 + T - 1) / T, T>>>(p_xw, p_dinv, p_cnt, p_rowst, p_csr, b1, p_h);

    // ---- conv2 ----
    k_gemm_hw2<<<(N_NODES + 255) / 256, 256>>>(p_h, W2, p_xw);
    k_aggr    <<<(N_NODES * 8 + T - 1) / T, T>>>(p_xw, p_dinv, p_cnt, p_rowst, p_csr, b2, p_h);

    // ---- heads ----
    k_head<<<(N_NODES + 63) / 64, 256>>>(p_h, pW1, pb1, pW2, pb2, vW1, vb1, vW2, vb2, out);
}